// round 4
// baseline (speedup 1.0000x reference)
#include <cuda_runtime.h>
#include <cstdint>
#include <math.h>

// ---------------------------------------------------------------------------
// MHRetention: x:(4,4096,1024) fp32
//   q = relu(x@Wq^T)/8 ; k = relu(x@Wk^T)/8 ; v = x@Wv^T ; u = silu(x@Wu^T)
//   per (b,h): kv = K^T V (64x64) ; out = Q @ kv ; SRMSNorm(out) * u
//   y = out @ Wo^T
// Round 1: full fp32 correctness baseline using packed fma.rn.f32x2 (FFMA2).
// ---------------------------------------------------------------------------

#define EMB_   1024
#define HEADS_ 16
#define HD_    64
#define B_     4
#define L_     4096
#define M_     (B_ * L_)   // 16384

// Scratch (device globals: no allocations allowed)
__device__ float g_q[(size_t)M_ * EMB_];
__device__ float g_k[(size_t)M_ * EMB_];
__device__ float g_v[(size_t)M_ * EMB_];
__device__ float g_u[(size_t)M_ * EMB_];
__device__ float g_o[(size_t)M_ * EMB_];
__device__ float g_kv[B_ * HEADS_ * HD_ * HD_];

// ---- packed f32x2 helpers (Blackwell FFMA2 path) --------------------------
__device__ __forceinline__ uint64_t pk2(float lo, float hi) {
    uint64_t r;
    asm("mov.b64 %0, {%1, %2};" : "=l"(r) : "f"(lo), "f"(hi));
    return r;
}
__device__ __forceinline__ void upk2(uint64_t v, float& lo, float& hi) {
    asm("mov.b64 {%0, %1}, %2;" : "=f"(lo), "=f"(hi) : "l"(v));
}
__device__ __forceinline__ void ffma2(uint64_t& c, uint64_t a, uint64_t b) {
    asm("fma.rn.f32x2 %0, %1, %2, %0;" : "+l"(c) : "l"(a), "l"(b));
}

template <int MODE>
__device__ __forceinline__ float act_fn(float v) {
    if (MODE == 1) return fmaxf(v, 0.0f) * 0.125f;          // relu / sqrt(64)
    if (MODE == 2) return v / (1.0f + expf(-v));            // silu
    return v;
}

// ---------------------------------------------------------------------------
// NT GEMM: C[m][n] = act( sum_k A[m][k] * Bw[n][k] ),  M=16384, N=K=1024.
// 128x128 block tile, BK=16, 256 threads, 8x8 per-thread microtile,
// accumulators packed as f32x2 pairs -> 32 FFMA2 per k-step per thread.
// ASRC: 0 -> Ain param, 1 -> g_o.  DST: 0..3 -> g_q/g_k/g_v/g_u, 4 -> Cext.
// ---------------------------------------------------------------------------
template <int MODE, int ASRC, int DST>
__global__ void __launch_bounds__(256, 2) gemm_nt(const float* __restrict__ Ain,
                                                  const float* __restrict__ Bw,
                                                  float* __restrict__ Cext)
{
    const int K = EMB_, N = EMB_;
    const float* A = (ASRC == 0) ? Ain : g_o;
    float* C;
    if      (DST == 0) C = g_q;
    else if (DST == 1) C = g_k;
    else if (DST == 2) C = g_v;
    else if (DST == 3) C = g_u;
    else               C = Cext;

    __shared__ __align__(16) float As[16][132];
    __shared__ __align__(16) float Bs[16][132];

    const int tid = threadIdx.x;
    const int m0 = blockIdx.y * 128;
    const int n0 = blockIdx.x * 128;
    const int tm = tid >> 4;   // 0..15
    const int tn = tid & 15;   // 0..15

    uint64_t c2[8][4];
#pragma unroll
    for (int i = 0; i < 8; i++)
#pragma unroll
        for (int j = 0; j < 4; j++) c2[i][j] = 0ull;

    for (int kt = 0; kt < K; kt += 16) {
#pragma unroll
        for (int s = 0; s < 2; s++) {
            int idx = tid + s * 256;
            int row = idx >> 2;
            int c4  = (idx & 3) * 4;
            float4 av = *(const float4*)(A  + (size_t)(m0 + row) * K + kt + c4);
            float4 bv = *(const float4*)(Bw + (size_t)(n0 + row) * K + kt + c4);
            As[c4 + 0][row] = av.x; As[c4 + 1][row] = av.y;
            As[c4 + 2][row] = av.z; As[c4 + 3][row] = av.w;
            Bs[c4 + 0][row] = bv.x; Bs[c4 + 1][row] = bv.y;
            Bs[c4 + 2][row] = bv.z; Bs[c4 + 3][row] = bv.w;
        }
        __syncthreads();
#pragma unroll
        for (int k = 0; k < 16; k++) {
            float4 b0 = *(const float4*)&Bs[k][tn * 8];
            float4 b1 = *(const float4*)&Bs[k][tn * 8 + 4];
            uint64_t bp[4];
            bp[0] = pk2(b0.x, b0.y); bp[1] = pk2(b0.z, b0.w);
            bp[2] = pk2(b1.x, b1.y); bp[3] = pk2(b1.z, b1.w);
#pragma unroll
            for (int i = 0; i < 8; i++) {
                float a = As[k][tm * 8 + i];
                uint64_t ad = pk2(a, a);
#pragma unroll
                for (int j = 0; j < 4; j++) ffma2(c2[i][j], ad, bp[j]);
            }
        }
        __syncthreads();
    }

#pragma unroll
    for (int i = 0; i < 8; i++) {
        float o[8];
#pragma unroll
        for (int j = 0; j < 4; j++) upk2(c2[i][j], o[2 * j], o[2 * j + 1]);
#pragma unroll
        for (int j = 0; j < 8; j++) o[j] = act_fn<MODE>(o[j]);
        size_t off = (size_t)(m0 + tm * 8 + i) * N + n0 + tn * 8;
        *(float4*)(C + off)     = make_float4(o[0], o[1], o[2], o[3]);
        *(float4*)(C + off + 4) = make_float4(o[4], o[5], o[6], o[7]);
    }
}

// ---------------------------------------------------------------------------
// kv state: g_kv[bh][kk][vv] = sum_l k[b,h,l,kk] * v[b,h,l,vv]
// grid: (64 l-chunks of 64 rows, 64 bh), atomicAdd partial outer products.
// ---------------------------------------------------------------------------
__global__ void zero_kv_kernel()
{
    int i = blockIdx.x * blockDim.x + threadIdx.x;
    if (i < B_ * HEADS_ * HD_ * HD_) g_kv[i] = 0.0f;
}

__global__ void __launch_bounds__(256) kv_kernel()
{
    const int bh = blockIdx.y;        // 0..63
    const int ch = blockIdx.x;        // 0..63 (64-row chunks)
    const int b = bh >> 4, h = bh & 15;

    __shared__ __align__(16) float Ks[64][64];
    __shared__ __align__(16) float Vs[64][64];

    const int tid = threadIdx.x;
    const size_t base = ((size_t)b * L_ + (size_t)ch * 64) * EMB_ + (size_t)h * HD_;

#pragma unroll
    for (int s = 0; s < 4; s++) {
        int idx = tid + s * 256;
        int row = idx >> 4;
        int c4  = (idx & 15) * 4;
        *(float4*)&Ks[row][c4] = *(const float4*)(g_k + base + (size_t)row * EMB_ + c4);
        *(float4*)&Vs[row][c4] = *(const float4*)(g_v + base + (size_t)row * EMB_ + c4);
    }
    __syncthreads();

    const int tk = (tid >> 4) * 4;    // 0..60
    const int tv = (tid & 15) * 4;    // 0..60
    float acc[4][4];
#pragma unroll
    for (int i = 0; i < 4; i++)
#pragma unroll
        for (int j = 0; j < 4; j++) acc[i][j] = 0.0f;

    for (int l = 0; l < 64; l++) {
        float4 ka = *(const float4*)&Ks[l][tk];
        float4 vb = *(const float4*)&Vs[l][tv];
        float a[4] = {ka.x, ka.y, ka.z, ka.w};
        float c[4] = {vb.x, vb.y, vb.z, vb.w};
#pragma unroll
        for (int i = 0; i < 4; i++)
#pragma unroll
            for (int j = 0; j < 4; j++) acc[i][j] = fmaf(a[i], c[j], acc[i][j]);
    }

    float* kvp = g_kv + (size_t)bh * HD_ * HD_;
#pragma unroll
    for (int i = 0; i < 4; i++)
#pragma unroll
        for (int j = 0; j < 4; j++)
            atomicAdd(kvp + (size_t)(tk + i) * HD_ + tv + j, acc[i][j]);
}

// ---------------------------------------------------------------------------
// retention: out[l][:] = q[l][:] @ kv ; SRMSNorm(out) ; out *= u ; -> g_o
// block: 64 rows, 256 threads (4 threads per row, 16 cols each).
// ---------------------------------------------------------------------------
__global__ void __launch_bounds__(256) ret_kernel()
{
    const int bh = blockIdx.y;
    const int ch = blockIdx.x;
    const int b = bh >> 4, h = bh & 15;

    __shared__ __align__(16) float KV[64][64];
    __shared__ __align__(16) float Qs[64][68];

    const int tid = threadIdx.x;
    const size_t base = ((size_t)b * L_ + (size_t)ch * 64) * EMB_ + (size_t)h * HD_;
    const float* kvp = g_kv + (size_t)bh * HD_ * HD_;

#pragma unroll
    for (int s = 0; s < 4; s++) {
        int idx = tid + s * 256;
        int row = idx >> 4;
        int c4  = (idx & 15) * 4;
        *(float4*)&KV[row][c4] = *(const float4*)(kvp + (size_t)row * 64 + c4);
        *(float4*)&Qs[row][c4] = *(const float4*)(g_q + base + (size_t)row * EMB_ + c4);
    }
    __syncthreads();

    const int r  = tid >> 2;          // 0..63 row in chunk
    const int qt = (tid & 3) * 16;    // column group

    float o[16];
#pragma unroll
    for (int j = 0; j < 16; j++) o[j] = 0.0f;

    for (int kk = 0; kk < 64; kk++) {
        float qv = Qs[r][kk];
#pragma unroll
        for (int j = 0; j < 16; j++) o[j] = fmaf(qv, KV[kk][qt + j], o[j]);
    }

    float ss = 0.0f;
#pragma unroll
    for (int j = 0; j < 16; j++) ss = fmaf(o[j], o[j], ss);
    ss += __shfl_xor_sync(0xffffffffu, ss, 1);
    ss += __shfl_xor_sync(0xffffffffu, ss, 2);

    float nrm = sqrtf(ss) * 0.125f;                 // ||o * (1/sqrt(64))||
    float inv = 1.0f / fmaxf(nrm, 1e-12f);

    size_t off = base + (size_t)r * EMB_ + qt;
#pragma unroll
    for (int j4 = 0; j4 < 4; j4++) {
        float4 uu = *(const float4*)(g_u + off + j4 * 4);
        float4 w;
        w.x = o[j4 * 4 + 0] * inv * uu.x;
        w.y = o[j4 * 4 + 1] * inv * uu.y;
        w.z = o[j4 * 4 + 2] * inv * uu.z;
        w.w = o[j4 * 4 + 3] * inv * uu.w;
        *(float4*)(g_o + off + j4 * 4) = w;
    }
}

// ---------------------------------------------------------------------------
extern "C" void kernel_launch(void* const* d_in, const int* in_sizes, int n_in,
                              void* d_out, int out_size)
{
    const float* x  = (const float*)d_in[0];
    const float* Wq = (const float*)d_in[1];
    const float* Wk = (const float*)d_in[2];
    const float* Wv = (const float*)d_in[3];
    const float* Wu = (const float*)d_in[4];
    const float* Wo = (const float*)d_in[5];
    float* out = (float*)d_out;

    dim3 gg(EMB_ / 128, M_ / 128);   // (8, 128)

    gemm_nt<1, 0, 0><<<gg, 256>>>(x, Wq, nullptr);   // q = relu(.)/8
    gemm_nt<1, 0, 1><<<gg, 256>>>(x, Wk, nullptr);   // k = relu(.)/8
    gemm_nt<0, 0, 2><<<gg, 256>>>(x, Wv, nullptr);   // v
    gemm_nt<2, 0, 3><<<gg, 256>>>(x, Wu, nullptr);   // u = silu(.)

    zero_kv_kernel<<<(B_ * HEADS_ * HD_ * HD_ + 255) / 256, 256>>>();
    kv_kernel<<<dim3(L_ / 64, B_ * HEADS_), 256>>>();
    ret_kernel<<<dim3(L_ / 64, B_ * HEADS_), 256>>>();

    gemm_nt<0, 1, 4><<<gg, 256>>>(nullptr, Wo, out); // y = o @ Wo^T
}

// round 5
// speedup vs baseline: 1.0009x; 1.0009x over previous
#include <cuda_runtime.h>
#include <cstdint>
#include <math.h>

// ---------------------------------------------------------------------------
// MHRetention: x:(4,4096,1024) fp32
//   q = relu(x@Wq^T)/8 ; k = relu(x@Wk^T)/8 ; v = x@Wv^T ; u = silu(x@Wu^T)
//   per (b,h): kv = K^T V (64x64) ; out = Q @ kv ; SRMSNorm(out) * u
//   y = out @ Wo^T
// Round 1: full fp32 correctness baseline using packed fma.rn.f32x2 (FFMA2).
// ---------------------------------------------------------------------------

#define EMB_   1024
#define HEADS_ 16
#define HD_    64
#define B_     4
#define L_     4096
#define M_     (B_ * L_)   // 16384

// Scratch (device globals: no allocations allowed)
__device__ float g_q[(size_t)M_ * EMB_];
__device__ float g_k[(size_t)M_ * EMB_];
__device__ float g_v[(size_t)M_ * EMB_];
__device__ float g_u[(size_t)M_ * EMB_];
__device__ float g_o[(size_t)M_ * EMB_];
__device__ float g_kv[B_ * HEADS_ * HD_ * HD_];

// ---- packed f32x2 helpers (Blackwell FFMA2 path) --------------------------
__device__ __forceinline__ uint64_t pk2(float lo, float hi) {
    uint64_t r;
    asm("mov.b64 %0, {%1, %2};" : "=l"(r) : "f"(lo), "f"(hi));
    return r;
}
__device__ __forceinline__ void upk2(uint64_t v, float& lo, float& hi) {
    asm("mov.b64 {%0, %1}, %2;" : "=f"(lo), "=f"(hi) : "l"(v));
}
__device__ __forceinline__ void ffma2(uint64_t& c, uint64_t a, uint64_t b) {
    asm("fma.rn.f32x2 %0, %1, %2, %0;" : "+l"(c) : "l"(a), "l"(b));
}

template <int MODE>
__device__ __forceinline__ float act_fn(float v) {
    if (MODE == 1) return fmaxf(v, 0.0f) * 0.125f;          // relu / sqrt(64)
    if (MODE == 2) return v / (1.0f + expf(-v));            // silu
    return v;
}

// ---------------------------------------------------------------------------
// NT GEMM: C[m][n] = act( sum_k A[m][k] * Bw[n][k] ),  M=16384, N=K=1024.
// 128x128 block tile, BK=16, 256 threads, 8x8 per-thread microtile,
// accumulators packed as f32x2 pairs -> 32 FFMA2 per k-step per thread.
// ASRC: 0 -> Ain param, 1 -> g_o.  DST: 0..3 -> g_q/g_k/g_v/g_u, 4 -> Cext.
// ---------------------------------------------------------------------------
template <int MODE, int ASRC, int DST>
__global__ void __launch_bounds__(256, 2) gemm_nt(const float* __restrict__ Ain,
                                                  const float* __restrict__ Bw,
                                                  float* __restrict__ Cext)
{
    const int K = EMB_, N = EMB_;
    const float* A = (ASRC == 0) ? Ain : g_o;
    float* C;
    if      (DST == 0) C = g_q;
    else if (DST == 1) C = g_k;
    else if (DST == 2) C = g_v;
    else if (DST == 3) C = g_u;
    else               C = Cext;

    __shared__ __align__(16) float As[16][132];
    __shared__ __align__(16) float Bs[16][132];

    const int tid = threadIdx.x;
    const int m0 = blockIdx.y * 128;
    const int n0 = blockIdx.x * 128;
    const int tm = tid >> 4;   // 0..15
    const int tn = tid & 15;   // 0..15

    uint64_t c2[8][4];
#pragma unroll
    for (int i = 0; i < 8; i++)
#pragma unroll
        for (int j = 0; j < 4; j++) c2[i][j] = 0ull;

    for (int kt = 0; kt < K; kt += 16) {
#pragma unroll
        for (int s = 0; s < 2; s++) {
            int idx = tid + s * 256;
            int row = idx >> 2;
            int c4  = (idx & 3) * 4;
            float4 av = *(const float4*)(A  + (size_t)(m0 + row) * K + kt + c4);
            float4 bv = *(const float4*)(Bw + (size_t)(n0 + row) * K + kt + c4);
            As[c4 + 0][row] = av.x; As[c4 + 1][row] = av.y;
            As[c4 + 2][row] = av.z; As[c4 + 3][row] = av.w;
            Bs[c4 + 0][row] = bv.x; Bs[c4 + 1][row] = bv.y;
            Bs[c4 + 2][row] = bv.z; Bs[c4 + 3][row] = bv.w;
        }
        __syncthreads();
#pragma unroll
        for (int k = 0; k < 16; k++) {
            float4 b0 = *(const float4*)&Bs[k][tn * 8];
            float4 b1 = *(const float4*)&Bs[k][tn * 8 + 4];
            uint64_t bp[4];
            bp[0] = pk2(b0.x, b0.y); bp[1] = pk2(b0.z, b0.w);
            bp[2] = pk2(b1.x, b1.y); bp[3] = pk2(b1.z, b1.w);
#pragma unroll
            for (int i = 0; i < 8; i++) {
                float a = As[k][tm * 8 + i];
                uint64_t ad = pk2(a, a);
#pragma unroll
                for (int j = 0; j < 4; j++) ffma2(c2[i][j], ad, bp[j]);
            }
        }
        __syncthreads();
    }

#pragma unroll
    for (int i = 0; i < 8; i++) {
        float o[8];
#pragma unroll
        for (int j = 0; j < 4; j++) upk2(c2[i][j], o[2 * j], o[2 * j + 1]);
#pragma unroll
        for (int j = 0; j < 8; j++) o[j] = act_fn<MODE>(o[j]);
        size_t off = (size_t)(m0 + tm * 8 + i) * N + n0 + tn * 8;
        *(float4*)(C + off)     = make_float4(o[0], o[1], o[2], o[3]);
        *(float4*)(C + off + 4) = make_float4(o[4], o[5], o[6], o[7]);
    }
}

// ---------------------------------------------------------------------------
// kv state: g_kv[bh][kk][vv] = sum_l k[b,h,l,kk] * v[b,h,l,vv]
// grid: (64 l-chunks of 64 rows, 64 bh), atomicAdd partial outer products.
// ---------------------------------------------------------------------------
__global__ void zero_kv_kernel()
{
    int i = blockIdx.x * blockDim.x + threadIdx.x;
    if (i < B_ * HEADS_ * HD_ * HD_) g_kv[i] = 0.0f;
}

__global__ void __launch_bounds__(256) kv_kernel()
{
    const int bh = blockIdx.y;        // 0..63
    const int ch = blockIdx.x;        // 0..63 (64-row chunks)
    const int b = bh >> 4, h = bh & 15;

    __shared__ __align__(16) float Ks[64][64];
    __shared__ __align__(16) float Vs[64][64];

    const int tid = threadIdx.x;
    const size_t base = ((size_t)b * L_ + (size_t)ch * 64) * EMB_ + (size_t)h * HD_;

#pragma unroll
    for (int s = 0; s < 4; s++) {
        int idx = tid + s * 256;
        int row = idx >> 4;
        int c4  = (idx & 15) * 4;
        *(float4*)&Ks[row][c4] = *(const float4*)(g_k + base + (size_t)row * EMB_ + c4);
        *(float4*)&Vs[row][c4] = *(const float4*)(g_v + base + (size_t)row * EMB_ + c4);
    }
    __syncthreads();

    const int tk = (tid >> 4) * 4;    // 0..60
    const int tv = (tid & 15) * 4;    // 0..60
    float acc[4][4];
#pragma unroll
    for (int i = 0; i < 4; i++)
#pragma unroll
        for (int j = 0; j < 4; j++) acc[i][j] = 0.0f;

    for (int l = 0; l < 64; l++) {
        float4 ka = *(const float4*)&Ks[l][tk];
        float4 vb = *(const float4*)&Vs[l][tv];
        float a[4] = {ka.x, ka.y, ka.z, ka.w};
        float c[4] = {vb.x, vb.y, vb.z, vb.w};
#pragma unroll
        for (int i = 0; i < 4; i++)
#pragma unroll
            for (int j = 0; j < 4; j++) acc[i][j] = fmaf(a[i], c[j], acc[i][j]);
    }

    float* kvp = g_kv + (size_t)bh * HD_ * HD_;
#pragma unroll
    for (int i = 0; i < 4; i++)
#pragma unroll
        for (int j = 0; j < 4; j++)
            atomicAdd(kvp + (size_t)(tk + i) * HD_ + tv + j, acc[i][j]);
}

// ---------------------------------------------------------------------------
// retention: out[l][:] = q[l][:] @ kv ; SRMSNorm(out) ; out *= u ; -> g_o
// block: 64 rows, 256 threads (4 threads per row, 16 cols each).
// ---------------------------------------------------------------------------
__global__ void __launch_bounds__(256) ret_kernel()
{
    const int bh = blockIdx.y;
    const int ch = blockIdx.x;
    const int b = bh >> 4, h = bh & 15;

    __shared__ __align__(16) float KV[64][64];
    __shared__ __align__(16) float Qs[64][68];

    const int tid = threadIdx.x;
    const size_t base = ((size_t)b * L_ + (size_t)ch * 64) * EMB_ + (size_t)h * HD_;
    const float* kvp = g_kv + (size_t)bh * HD_ * HD_;

#pragma unroll
    for (int s = 0; s < 4; s++) {
        int idx = tid + s * 256;
        int row = idx >> 4;
        int c4  = (idx & 15) * 4;
        *(float4*)&KV[row][c4] = *(const float4*)(kvp + (size_t)row * 64 + c4);
        *(float4*)&Qs[row][c4] = *(const float4*)(g_q + base + (size_t)row * EMB_ + c4);
    }
    __syncthreads();

    const int r  = tid >> 2;          // 0..63 row in chunk
    const int qt = (tid & 3) * 16;    // column group

    float o[16];
#pragma unroll
    for (int j = 0; j < 16; j++) o[j] = 0.0f;

    for (int kk = 0; kk < 64; kk++) {
        float qv = Qs[r][kk];
#pragma unroll
        for (int j = 0; j < 16; j++) o[j] = fmaf(qv, KV[kk][qt + j], o[j]);
    }

    float ss = 0.0f;
#pragma unroll
    for (int j = 0; j < 16; j++) ss = fmaf(o[j], o[j], ss);
    ss += __shfl_xor_sync(0xffffffffu, ss, 1);
    ss += __shfl_xor_sync(0xffffffffu, ss, 2);

    float nrm = sqrtf(ss) * 0.125f;                 // ||o * (1/sqrt(64))||
    float inv = 1.0f / fmaxf(nrm, 1e-12f);

    size_t off = base + (size_t)r * EMB_ + qt;
#pragma unroll
    for (int j4 = 0; j4 < 4; j4++) {
        float4 uu = *(const float4*)(g_u + off + j4 * 4);
        float4 w;
        w.x = o[j4 * 4 + 0] * inv * uu.x;
        w.y = o[j4 * 4 + 1] * inv * uu.y;
        w.z = o[j4 * 4 + 2] * inv * uu.z;
        w.w = o[j4 * 4 + 3] * inv * uu.w;
        *(float4*)(g_o + off + j4 * 4) = w;
    }
}

// ---------------------------------------------------------------------------
extern "C" void kernel_launch(void* const* d_in, const int* in_sizes, int n_in,
                              void* d_out, int out_size)
{
    const float* x  = (const float*)d_in[0];
    const float* Wq = (const float*)d_in[1];
    const float* Wk = (const float*)d_in[2];
    const float* Wv = (const float*)d_in[3];
    const float* Wu = (const float*)d_in[4];
    const float* Wo = (const float*)d_in[5];
    float* out = (float*)d_out;

    dim3 gg(EMB_ / 128, M_ / 128);   // (8, 128)

    gemm_nt<1, 0, 0><<<gg, 256>>>(x, Wq, nullptr);   // q = relu(.)/8
    gemm_nt<1, 0, 1><<<gg, 256>>>(x, Wk, nullptr);   // k = relu(.)/8
    gemm_nt<0, 0, 2><<<gg, 256>>>(x, Wv, nullptr);   // v
    gemm_nt<2, 0, 3><<<gg, 256>>>(x, Wu, nullptr);   // u = silu(.)

    zero_kv_kernel<<<(B_ * HEADS_ * HD_ * HD_ + 255) / 256, 256>>>();
    kv_kernel<<<dim3(L_ / 64, B_ * HEADS_), 256>>>();
    ret_kernel<<<dim3(L_ / 64, B_ * HEADS_), 256>>>();

    gemm_nt<0, 1, 4><<<gg, 256>>>(nullptr, Wo, out); // y = o @ Wo^T
}